// round 13
// baseline (speedup 1.0000x reference)
#include <cuda_runtime.h>
#include <cuda_fp16.h>
#include <math.h>
#include <stdint.h>

#define BB 2
#define TT 2048
#define CC 1024
#define NH 16
#define HD 64
#define BH (BB*NH)

// scratch — fp16, fragment-permuted + row-parity chunk-swizzled, TILE-PACKED
__device__ __half g_q[(size_t)BH * TT * HD];      // [bh][t][d_pos] (no swizzle; LDG reads)
__device__ __half g_k[(size_t)BH * TT * HD];      // [bh][t][d_pos ^ ((t&1)<<5)]
__device__ __half g_vt[(size_t)BH * HD * TT];     // [bh][kt][d][t_pos ^ ((d&1)<<5)] 64x64 tiles
__device__ __half g_att[(size_t)BH * TT * HD];    // [bh][t][d_pos ^ ((t&1)<<5)]
__device__ __half g_xt[(size_t)BB * TT * CC];     // [mt*16+kt][128][64] tiles, row-swizzled
__device__ __half g_wqkvT[(size_t)3 * CC * CC];   // [nt*16+kt][128][64] tiles
__device__ __half g_wprojT[(size_t)CC * CC];      // [nt*16+kt][128][64] tiles

// perm within 32-chunk: k = 16h+8b+2g+l -> pos = g*8 + 4h + 2b + l
__device__ __forceinline__ int hpos(int k) {
    return (k & ~31) + (((k >> 1) & 3) << 3) + (((k >> 4) & 1) << 2)
         + (((k >> 3) & 1) << 1) + (k & 1);
}

__device__ __forceinline__ uint32_t h2u(__half2 h) { return *(uint32_t*)&h; }

__device__ __forceinline__ uint32_t smem_to_u32(const void* p) {
    uint32_t a;
    asm("{ .reg .u64 t; cvta.to.shared.u64 t, %1; cvt.u32.u64 %0, t; }" : "=r"(a) : "l"(p));
    return a;
}

__device__ __forceinline__ void mma16(float* c,
                                      uint32_t a0, uint32_t a1, uint32_t a2, uint32_t a3,
                                      uint32_t b0, uint32_t b1) {
    asm volatile(
        "mma.sync.aligned.m16n8k16.row.col.f32.f16.f16.f32 "
        "{%0,%1,%2,%3}, {%4,%5,%6,%7}, {%8,%9}, {%0,%1,%2,%3};"
        : "+f"(c[0]), "+f"(c[1]), "+f"(c[2]), "+f"(c[3])
        : "r"(a0), "r"(a1), "r"(a2), "r"(a3), "r"(b0), "r"(b1));
}

// ---- bulk copy + mbarrier ----
__device__ __forceinline__ void bulk_g2s(uint32_t dst, const void* src, uint32_t bytes,
                                         uint32_t mbar) {
    asm volatile(
        "cp.async.bulk.shared::cluster.global.mbarrier::complete_tx::bytes [%0], [%1], %2, [%3];"
        :: "r"(dst), "l"(src), "r"(bytes), "r"(mbar) : "memory");
}
#define MBARRIER_INIT(mbar, cnt) \
    asm volatile("mbarrier.init.shared.b64 [%0], %1;" \
                 :: "r"((uint32_t)(mbar)), "r"((uint32_t)(cnt)) : "memory")
#define MBARRIER_EXPECT_TX(mbar, bytes) \
    asm volatile("mbarrier.arrive.expect_tx.shared.b64 _, [%0], %1;" \
                 :: "r"((uint32_t)(mbar)), "r"((uint32_t)(bytes)) : "memory")
#define MBARRIER_WAIT_PARITY(mbar_smem_addr, phase_parity) do { \
    uint32_t _mbar = (uint32_t)(mbar_smem_addr); \
    uint32_t _parity = (uint32_t)(phase_parity); \
    uint32_t _done; \
    asm volatile( \
        "{\n\t.reg .pred p;\n\t" \
        "mbarrier.try_wait.parity.acquire.cta.shared::cta.b64 p, [%1], %2;\n\t" \
        "selp.b32 %0, 1, 0, p;\n\t}" \
        : "=r"(_done) : "r"(_mbar), "r"(_parity) : "memory"); \
    if (!_done) { \
        asm volatile( \
            "{\n\t.reg .pred P1;\n\t" \
            "WAIT_LOOP_%=:\n\t" \
            "mbarrier.try_wait.parity.acquire.cta.shared::cta.b64 P1, [%0], %1, 0x989680;\n\t" \
            "@P1 bra.uni WAIT_DONE_%=;\n\t" \
            "bra.uni WAIT_LOOP_%=;\n\t" \
            "WAIT_DONE_%=:\n\t}" \
            :: "r"(_mbar), "r"(_parity) : "memory"); \
    } \
} while(0)

// ---------------------------------------------------------------------------
// pre-pass: x fp32 [m][1024] -> g_xt fp16 tiled [mt*16+kt][128][64] swizzled
// ---------------------------------------------------------------------------
__global__ __launch_bounds__(256) void cvt_x_kernel(const float* __restrict__ in,
                                                    __half* __restrict__ out)
{
    int gid = blockIdx.x * 256 + threadIdx.x;     // unit of 8 halves
    int row = gid >> 7;
    int uc = gid & 127;
    int cb = (uc >> 2) << 5;                      // chunk base k (mult of 32)
    int g = uc & 3;
    const float* src = in + (size_t)row * CC + cb + 2 * g;
    float2 v0 = *(const float2*)(src);
    float2 v1 = *(const float2*)(src + 8);
    float2 v2 = *(const float2*)(src + 16);
    float2 v3 = *(const float2*)(src + 24);
    uint4 o;
    o.x = h2u(__floats2half2_rn(v0.x, v0.y));
    o.y = h2u(__floats2half2_rn(v1.x, v1.y));
    o.z = h2u(__floats2half2_rn(v2.x, v2.y));
    o.w = h2u(__floats2half2_rn(v3.x, v3.y));
    int mt = row >> 7, kt = cb >> 6, r = row & 127;
    int ch = ((cb >> 5) & 1) ^ (r & 1);
    *(uint4*)(out + ((size_t)(mt * 16 + kt) << 13) + (r << 6) + (ch << 5) + g * 8) = o;
}

// pre-pass: W fp32 [K=1024][N] -> tiled fp16 [nt*16+kt][128][64] swizzled
__global__ __launch_bounds__(128) void transpose_h_kernel(const float* __restrict__ in,
                                                          __half* __restrict__ out,
                                                          int N)
{
    __shared__ float t[32][33];
    const int k0 = blockIdx.y << 5, n0 = blockIdx.x << 5;
    const int tid = threadIdx.x;
    #pragma unroll
    for (int i = 0; i < 8; i++) {
        int idx = i * 128 + tid;
        int r = idx >> 5, c = idx & 31;
        t[r][c] = in[(size_t)(k0 + r) * N + n0 + c];
    }
    __syncthreads();
    int nl = tid >> 2, g = tid & 3;
    uint4 o;
    o.x = h2u(__floats2half2_rn(t[2*g][nl],      t[2*g+1][nl]));
    o.y = h2u(__floats2half2_rn(t[2*g+8][nl],    t[2*g+9][nl]));
    o.z = h2u(__floats2half2_rn(t[2*g+16][nl],   t[2*g+17][nl]));
    o.w = h2u(__floats2half2_rn(t[2*g+24][nl],   t[2*g+25][nl]));
    int n = n0 + nl;
    int nt = n >> 7, kt = k0 >> 6, r = n & 127;
    int ch = ((k0 >> 5) & 1) ^ (r & 1);
    *(uint4*)(out + ((size_t)(nt * 16 + kt) << 13) + (r << 6) + (ch << 5) + g * 8) = o;
}

// ---------------------------------------------------------------------------
// fp16 GEMM compute, WIDE warp tile 64x64 (4 warps 2x2, 128 threads).
// Tiles [128 rows][128 B], row-parity chunk swizzle. sxor = (gi&1)<<6.
// Per iter/warp: 32 lds.128 (16 KB) feeding 128 mma -> 128 B/mma.
// ---------------------------------------------------------------------------
#define TILE_B 16384

#define GEMM_COMPUTE16W(Asb, Bsb)                                                \
    _Pragma("unroll")                                                            \
    for (int kc = 0; kc < 2; kc++) {                                             \
        const int co = (kc * 64 + gc * 16) ^ sxor;                               \
        uint4 alo[4], ahi[4], bf[8];                                             \
        _Pragma("unroll")                                                        \
        for (int tm = 0; tm < 4; tm++) {                                         \
            int r = wm + tm * 16 + gi;                                           \
            alo[tm] = *(const uint4*)((Asb) + r * 128 + co);                     \
            ahi[tm] = *(const uint4*)((Asb) + (r + 8) * 128 + co);               \
        }                                                                        \
        _Pragma("unroll")                                                        \
        for (int tn = 0; tn < 8; tn++) {                                         \
            int n = wn + tn * 8 + gi;                                            \
            bf[tn] = *(const uint4*)((Bsb) + n * 128 + co);                      \
        }                                                                        \
        _Pragma("unroll")                                                        \
        for (int tm = 0; tm < 4; tm++)                                           \
            _Pragma("unroll")                                                    \
            for (int tn = 0; tn < 8; tn++) {                                     \
                mma16(C[tm][tn], alo[tm].x, ahi[tm].x, alo[tm].y, ahi[tm].y,     \
                      bf[tn].x, bf[tn].y);                                       \
                mma16(C[tm][tn], alo[tm].z, ahi[tm].z, alo[tm].w, ahi[tm].w,     \
                      bf[tn].z, bf[tn].w);                                       \
            }                                                                    \
    }

#define GEMM_SMEM (128 + 6*TILE_B)   // 98432 B

// ---------------------------------------------------------------------------
// Kernel 1: QKV GEMM (fp16, bulk-copy 3-stage, 128 thr, warp tile 64x64)
// ---------------------------------------------------------------------------
__global__ __launch_bounds__(128, 2) void qkv_mma_kernel(const float* __restrict__ bias)
{
    extern __shared__ char smc[];
    const uint32_t sb = smem_to_u32(smc);
    const char* tA = smc + 128;
    const char* tB = smc + 128 + 3 * TILE_B;

    const int tid  = threadIdx.x;
    const int lane = tid & 31;
    const int warp = tid >> 5;
    const int gi = lane >> 2, gc = lane & 3;
    const int sxor = (gi & 1) << 6;
    const int wm = (warp >> 1) * 64;
    const int wn = (warp & 1) * 64;
    const int m0 = blockIdx.y * 128, n0 = blockIdx.x * 128;

    if (tid == 0) {
        MBARRIER_INIT(sb + 0, 1);
        MBARRIER_INIT(sb + 8, 1);
        MBARRIER_INIT(sb + 16, 1);
    }
    __syncthreads();

#define Q_ISSUE(s, kt)                                                          \
    {                                                                           \
        MBARRIER_EXPECT_TX(sb + 8 * (s), 2 * TILE_B);                           \
        bulk_g2s(sb + 128 + (s) * TILE_B,                                       \
                 g_xt + ((size_t)(blockIdx.y * 16 + (kt)) << 13), TILE_B,       \
                 sb + 8 * (s));                                                 \
        bulk_g2s(sb + 128 + 3 * TILE_B + (s) * TILE_B,                          \
                 g_wqkvT + ((size_t)(blockIdx.x * 16 + (kt)) << 13), TILE_B,    \
                 sb + 8 * (s));                                                 \
    }

    if (tid == 0) { Q_ISSUE(0, 0); Q_ISSUE(1, 1); }

    float C[4][8][4] = {};
    int ph0 = 0, ph1 = 0, ph2 = 0;

    for (int it = 0; it < 16; it++) {
        const int s = it % 3;
        int ph = (s == 0) ? ph0 : (s == 1) ? ph1 : ph2;
        MBARRIER_WAIT_PARITY(sb + 8 * s, ph);
        if (s == 0) ph0 ^= 1; else if (s == 1) ph1 ^= 1; else ph2 ^= 1;
        __syncthreads();           // all warps done reading stage (it+2)%3
        if (tid == 0 && it + 2 < 16) { int s2 = (it + 2) % 3; Q_ISSUE(s2, it + 2); }
        const char* Asb = tA + s * TILE_B;
        const char* Bsb = tB + s * TILE_B;
        GEMM_COMPUTE16W(Asb, Bsb);
    }

    // epilogue: bias, scatter fp16 into q/k/vt (swizzled layouts)
    #pragma unroll
    for (int tm = 0; tm < 4; tm++) {
        #pragma unroll
        for (int tn = 0; tn < 8; tn++) {
            #pragma unroll
            for (int half_ = 0; half_ < 2; half_++) {
                int m = m0 + wm + tm * 16 + gi + half_ * 8;
                int n = n0 + wn + tn * 8 + 2 * gc;       // even; pair (n, n+1)
                float v0 = C[tm][tn][half_ * 2 + 0] + bias[n];
                float v1 = C[tm][tn][half_ * 2 + 1] + bias[n + 1];
                int b = m >> 11, t = m & 2047;
                int h = n / 192;
                int r = n - h * 192;
                int d = r & 63;                           // even
                int bh = (b << 4) + h;
                if (r < 64) {
                    __half2 hv = __floats2half2_rn(v0 * 0.125f, v1 * 0.125f);
                    *(__half2*)(g_q + ((size_t)bh << 17) + ((size_t)t << 6) + hpos(d)) = hv;
                } else if (r < 128) {
                    __half2 hv = __floats2half2_rn(v0, v1);
                    int pos = hpos(d) ^ ((t & 1) << 5);
                    *(__half2*)(g_k + ((size_t)bh << 17) + ((size_t)t << 6) + pos) = hv;
                } else {
                    size_t tbase = ((size_t)(bh * 32 + (t >> 6)) << 12);
                    int tp = hpos(t & 63);
                    g_vt[tbase + ((size_t)d << 6) + tp]              = __float2half_rn(v0);
                    g_vt[tbase + ((size_t)(d + 1) << 6) + (tp ^ 32)] = __float2half_rn(v1);
                }
            }
        }
    }
}

// ---------------------------------------------------------------------------
// Kernel 2: causal flash attention (fp16, bulk-copy 2-stage, P in registers)
// — unchanged from R12
// ---------------------------------------------------------------------------
#define KTILE_B 8192
#define ATTN_SMEM (128 + 4*KTILE_B)   // 32896 B

__global__ __launch_bounds__(256, 2) void attn_mma_kernel()
{
    extern __shared__ char smc[];
    const uint32_t sb = smem_to_u32(smc);
    const char* tK  = smc + 128;
    const char* tVt = smc + 128 + 2 * KTILE_B;

    const int bh = blockIdx.y;
    const int tid = threadIdx.x;
    const int lane = tid & 31;
    const int warp = tid >> 5;
    const int gi = lane >> 2, gc = lane & 3;
    const int sxor = (gi & 1) << 6;
    const int i0 = warp * 16 + gi;

    const __half* Kg  = g_k  + ((size_t)bh << 17);
    const __half* Vtg = g_vt + ((size_t)bh << 17);

    if (tid == 0) { MBARRIER_INIT(sb + 0, 1); MBARRIER_INIT(sb + 8, 1); }
    __syncthreads();

    int islot = 0, wslot = 0, phw0 = 0, phw1 = 0;

#define A_ISSUE(kt)                                                             \
    {                                                                           \
        int s_ = islot & 1;                                                     \
        if (tid == 0) {                                                         \
            MBARRIER_EXPECT_TX(sb + 8 * s_, 2 * KTILE_B);                       \
            bulk_g2s(sb + 128 + s_ * KTILE_B, Kg + ((size_t)(kt) << 12),        \
                     KTILE_B, sb + 8 * s_);                                     \
            bulk_g2s(sb + 128 + 2 * KTILE_B + s_ * KTILE_B,                     \
                     Vtg + ((size_t)(kt) << 12), KTILE_B, sb + 8 * s_);         \
        }                                                                       \
        islot++;                                                                \
    }

    for (int pi = 0; pi < 2; pi++) {
        const int qt = pi ? (15 - (int)blockIdx.x) : (int)blockIdx.x;
        const int ktmax = 2 * qt + 1;
        const __half* Qg = g_q + ((size_t)bh << 17) + ((size_t)qt << 13);

        __syncthreads();
        A_ISSUE(0);

        uint4 qa[2], qb[2];
        #pragma unroll
        for (int qc = 0; qc < 2; qc++) {
            qa[qc] = *(const uint4*)(Qg + i0 * 64 + qc * 32 + gc * 8);
            qb[qc] = *(const uint4*)(Qg + (i0 + 8) * 64 + qc * 32 + gc * 8);
        }

        float O[8][4] = {};
        float m0r = -1e30f, m1r = -1e30f, l0r = 0.f, l1r = 0.f;

        for (int kt = 0; kt <= ktmax; kt++) {
            const int s = wslot & 1;
            int ph = s ? phw1 : phw0;
            MBARRIER_WAIT_PARITY(sb + 8 * s, ph);
            if (s) phw1 ^= 1; else phw0 ^= 1;
            wslot++;
            __syncthreads();
            if (kt < ktmax) A_ISSUE(kt + 1);

            const bool active = (kt * 64 <= qt * 128 + warp * 16 + 15);
            if (active) {
                const char* sKb  = tK + s * KTILE_B;
                const char* sVtb = tVt + s * KTILE_B;

                float S[8][4] = {};
                #pragma unroll
                for (int qc = 0; qc < 2; qc++) {
                    const int co = (qc * 64 + gc * 16) ^ sxor;
                    #pragma unroll
                    for (int nt = 0; nt < 8; nt++) {
                        int n = nt * 8 + gi;
                        uint4 kb = *(const uint4*)(sKb + n * 128 + co);
                        mma16(S[nt], qa[qc].x, qb[qc].x, qa[qc].y, qb[qc].y, kb.x, kb.y);
                        mma16(S[nt], qa[qc].z, qb[qc].z, qa[qc].w, qb[qc].w, kb.z, kb.w);
                    }
                }

                if (kt >= 2 * qt) {
                    int ig0 = qt * 128 + i0;
                    #pragma unroll
                    for (int nt = 0; nt < 8; nt++) {
                        int j0 = kt * 64 + nt * 8 + 2 * gc;
                        if (j0 > ig0)         S[nt][0] = -1e30f;
                        if (j0 + 1 > ig0)     S[nt][1] = -1e30f;
                        if (j0 > ig0 + 8)     S[nt][2] = -1e30f;
                        if (j0 + 1 > ig0 + 8) S[nt][3] = -1e30f;
                    }
                }

                float mx0 = -1e30f, mx1 = -1e30f;
                #pragma unroll
                for (int nt = 0; nt < 8; nt++) {
                    mx0 = fmaxf(mx0, fmaxf(S[nt][0], S[nt][1]));
                    mx1 = fmaxf(mx1, fmaxf(S[nt][2], S[nt][3]));
                }
                mx0 = fmaxf(mx0, __shfl_xor_sync(0xffffffffu, mx0, 1));
                mx0 = fmaxf(mx0, __shfl_xor_sync(0xffffffffu, mx0, 2));
                mx1 = fmaxf(mx1, __shfl_xor_sync(0xffffffffu, mx1, 1));
                mx1 = fmaxf(mx1, __shfl_xor_sync(0xffffffffu, mx1, 2));

                float mn0 = fmaxf(m0r, mx0), mn1 = fmaxf(m1r, mx1);
                float c0 = __expf(m0r - mn0), c1 = __expf(m1r - mn1);

                uint32_t phL[8], phH[8];
                float ls0 = 0.f, ls1 = 0.f;
                #pragma unroll
                for (int nt = 0; nt < 8; nt++) {
                    float p0 = __expf(S[nt][0] - mn0);
                    float p1 = __expf(S[nt][1] - mn0);
                    float p2 = __expf(S[nt][2] - mn1);
                    float p3 = __expf(S[nt][3] - mn1);
                    ls0 += p0 + p1;
                    ls1 += p2 + p3;
                    phL[nt] = h2u(__floats2half2_rn(p0, p1));
                    phH[nt] = h2u(__floats2half2_rn(p2, p3));
                }
                ls0 += __shfl_xor_sync(0xffffffffu, ls0, 1);
                ls0 += __shfl_xor_sync(0xffffffffu, ls0, 2);
                ls1 += __shfl_xor_sync(0xffffffffu, ls1, 1);
                ls1 += __shfl_xor_sync(0xffffffffu, ls1, 2);
                l0r = l0r * c0 + ls0;
                l1r = l1r * c1 + ls1;
                m0r = mn0; m1r = mn1;

                #pragma unroll
                for (int nt = 0; nt < 8; nt++) {
                    O[nt][0] *= c0; O[nt][1] *= c0;
                    O[nt][2] *= c1; O[nt][3] *= c1;
                }

                #pragma unroll
                for (int c = 0; c < 2; c++) {
                    const int co = (c * 64 + gc * 16) ^ sxor;
                    uint4 vb[8];
                    #pragma unroll
                    for (int ntd = 0; ntd < 8; ntd++)
                        vb[ntd] = *(const uint4*)(sVtb + (ntd * 8 + gi) * 128 + co);
                    #pragma unroll
                    for (int h = 0; h < 2; h++) {
                        int q0 = 4 * c + 2 * h;
                        uint32_t a0 = phL[q0], a1 = phH[q0];
                        uint32_t a2 = phL[q0 + 1], a3 = phH[q0 + 1];
                        #pragma unroll
                        for (int ntd = 0; ntd < 8; ntd++)
                            mma16(O[ntd], a0, a1, a2, a3,
                                  h ? vb[ntd].z : vb[ntd].x,
                                  h ? vb[ntd].w : vb[ntd].y);
                    }
                }
            }
        }

        float inv0 = 1.f / l0r, inv1 = 1.f / l1r;
        __half* Og = g_att + ((size_t)bh << 17) + ((size_t)qt << 13);
        #pragma unroll
        for (int nt = 0; nt < 8; nt++) {
            int d0 = nt * 8 + 2 * gc;      // even
            int pos = hpos(d0) ^ ((i0 & 1) << 5);
            *(__half2*)(Og + i0 * 64 + pos) =
                __floats2half2_rn(O[nt][0] * inv0, O[nt][1] * inv0);
            *(__half2*)(Og + (i0 + 8) * 64 + pos) =
                __floats2half2_rn(O[nt][2] * inv1, O[nt][3] * inv1);
        }
    }
}

// ---------------------------------------------------------------------------
// Kernel 3: proj GEMM (fp16, bulk-copy 3-stage, 128 thr, warp tile 64x64)
// ---------------------------------------------------------------------------
__global__ __launch_bounds__(128, 2) void proj_mma_kernel(const float* __restrict__ bias,
                                                          float* __restrict__ out)
{
    extern __shared__ char smc[];
    const uint32_t sb = smem_to_u32(smc);
    const char* tA = smc + 128;
    const char* tB = smc + 128 + 3 * TILE_B;

    const int tid  = threadIdx.x;
    const int lane = tid & 31;
    const int warp = tid >> 5;
    const int gi = lane >> 2, gc = lane & 3;
    const int sxor = (gi & 1) << 6;
    const int wm = (warp >> 1) * 64;
    const int wn = (warp & 1) * 64;
    const int m0 = blockIdx.y * 128, n0 = blockIdx.x * 128;
    const int bb = m0 >> 11, t0 = m0 & 2047;

    if (tid == 0) {
        MBARRIER_INIT(sb + 0, 1);
        MBARRIER_INIT(sb + 8, 1);
        MBARRIER_INIT(sb + 16, 1);
    }
    __syncthreads();

#define P_ISSUE(s, it_)                                                          \
    {                                                                            \
        MBARRIER_EXPECT_TX(sb + 8 * (s), 2 * TILE_B);                            \
        bulk_g2s(sb + 128 + (s) * TILE_B,                                        \
                 g_att + ((size_t)((bb << 4) + (it_)) << 17) + (size_t)t0 * 64,  \
                 TILE_B, sb + 8 * (s));                                          \
        bulk_g2s(sb + 128 + 3 * TILE_B + (s) * TILE_B,                           \
                 g_wprojT + ((size_t)(blockIdx.x * 16 + (it_)) << 13), TILE_B,   \
                 sb + 8 * (s));                                                  \
    }

    if (tid == 0) { P_ISSUE(0, 0); P_ISSUE(1, 1); }

    float C[4][8][4] = {};
    int ph0 = 0, ph1 = 0, ph2 = 0;

    for (int it = 0; it < 16; it++) {
        const int s = it % 3;
        int ph = (s == 0) ? ph0 : (s == 1) ? ph1 : ph2;
        MBARRIER_WAIT_PARITY(sb + 8 * s, ph);
        if (s == 0) ph0 ^= 1; else if (s == 1) ph1 ^= 1; else ph2 ^= 1;
        __syncthreads();
        if (tid == 0 && it + 2 < 16) { int s2 = (it + 2) % 3; P_ISSUE(s2, it + 2); }
        const char* Asb = tA + s * TILE_B;
        const char* Bsb = tB + s * TILE_B;
        GEMM_COMPUTE16W(Asb, Bsb);
    }

    #pragma unroll
    for (int tm = 0; tm < 4; tm++) {
        #pragma unroll
        for (int tn = 0; tn < 8; tn++) {
            #pragma unroll
            for (int e = 0; e < 4; e++) {
                int mm = m0 + wm + tm * 16 + gi + ((e >= 2) ? 8 : 0);
                int n = n0 + wn + tn * 8 + 2 * gc + (e & 1);
                out[(size_t)mm * CC + n] = C[tm][tn][e] + bias[n];
            }
        }
    }
}

// ---------------------------------------------------------------------------
extern "C" void kernel_launch(void* const* d_in, const int* in_sizes, int n_in,
                              void* d_out, int out_size)
{
    const float* x     = (const float*)d_in[0];
    const float* Wqkv  = (const float*)d_in[1];
    const float* bqkv  = (const float*)d_in[2];
    const float* Wproj = (const float*)d_in[3];
    const float* bproj = (const float*)d_in[4];
    float* out = (float*)d_out;

    cudaFuncSetAttribute(qkv_mma_kernel,
                         cudaFuncAttributeMaxDynamicSharedMemorySize, GEMM_SMEM);
    cudaFuncSetAttribute(proj_mma_kernel,
                         cudaFuncAttributeMaxDynamicSharedMemorySize, GEMM_SMEM);
    cudaFuncSetAttribute(attn_mma_kernel,
                         cudaFuncAttributeMaxDynamicSharedMemorySize, ATTN_SMEM);

    __half* xt; __half* wq; __half* wp;
    cudaGetSymbolAddress((void**)&xt, g_xt);
    cudaGetSymbolAddress((void**)&wq, g_wqkvT);
    cudaGetSymbolAddress((void**)&wp, g_wprojT);

    cvt_x_kernel<<<2048, 256>>>(x, xt);
    transpose_h_kernel<<<dim3(96, 32), 128>>>(Wqkv, wq, 3 * CC);
    transpose_h_kernel<<<dim3(32, 32), 128>>>(Wproj, wp, CC);

    qkv_mma_kernel<<<dim3(24, 32), 128, GEMM_SMEM>>>(bqkv);
    attn_mma_kernel<<<dim3(8, 32), 256, ATTN_SMEM>>>();
    proj_mma_kernel<<<dim3(8, 32), 128, GEMM_SMEM>>>(bproj, out);
}

// round 14
// speedup vs baseline: 1.0475x; 1.0475x over previous
#include <cuda_runtime.h>
#include <cuda_fp16.h>
#include <math.h>
#include <stdint.h>

#define BB 2
#define TT 2048
#define CC 1024
#define NH 16
#define HD 64
#define BH (BB*NH)

// scratch — fp16, fragment-permuted + row-parity chunk-swizzled, TILE-PACKED
__device__ __half g_q[(size_t)BH * TT * HD];      // [bh][t][d_pos]
__device__ __half g_k[(size_t)BH * TT * HD];      // [bh][t][d_pos ^ ((t&1)<<5)]
__device__ __half g_vt[(size_t)BH * HD * TT];     // [bh][kt][d][t_pos ^ ((d&1)<<5)] 64x64 tiles
__device__ __half g_att[(size_t)BH * TT * HD];    // [bh][t][d_pos ^ ((t&1)<<5)]
__device__ __half g_xt[(size_t)BB * TT * CC];     // [mt*16+kt][128][64] tiles
__device__ __half g_wqkvT[(size_t)3 * CC * CC];   // [nt*16+kt][128][64] tiles
__device__ __half g_wprojT[(size_t)CC * CC];      // [nt*16+kt][128][64] tiles

__device__ __forceinline__ int hpos(int k) {
    return (k & ~31) + (((k >> 1) & 3) << 3) + (((k >> 4) & 1) << 2)
         + (((k >> 3) & 1) << 1) + (k & 1);
}

__device__ __forceinline__ uint32_t h2u(__half2 h) { return *(uint32_t*)&h; }

__device__ __forceinline__ uint32_t smem_to_u32(const void* p) {
    uint32_t a;
    asm("{ .reg .u64 t; cvta.to.shared.u64 t, %1; cvt.u32.u64 %0, t; }" : "=r"(a) : "l"(p));
    return a;
}

__device__ __forceinline__ void mma16(float* c,
                                      uint32_t a0, uint32_t a1, uint32_t a2, uint32_t a3,
                                      uint32_t b0, uint32_t b1) {
    asm volatile(
        "mma.sync.aligned.m16n8k16.row.col.f32.f16.f16.f32 "
        "{%0,%1,%2,%3}, {%4,%5,%6,%7}, {%8,%9}, {%0,%1,%2,%3};"
        : "+f"(c[0]), "+f"(c[1]), "+f"(c[2]), "+f"(c[3])
        : "r"(a0), "r"(a1), "r"(a2), "r"(a3), "r"(b0), "r"(b1));
}

__device__ __forceinline__ void bulk_g2s(uint32_t dst, const void* src, uint32_t bytes,
                                         uint32_t mbar) {
    asm volatile(
        "cp.async.bulk.shared::cluster.global.mbarrier::complete_tx::bytes [%0], [%1], %2, [%3];"
        :: "r"(dst), "l"(src), "r"(bytes), "r"(mbar) : "memory");
}
#define MBARRIER_INIT(mbar, cnt) \
    asm volatile("mbarrier.init.shared.b64 [%0], %1;" \
                 :: "r"((uint32_t)(mbar)), "r"((uint32_t)(cnt)) : "memory")
#define MBARRIER_EXPECT_TX(mbar, bytes) \
    asm volatile("mbarrier.arrive.expect_tx.shared.b64 _, [%0], %1;" \
                 :: "r"((uint32_t)(mbar)), "r"((uint32_t)(bytes)) : "memory")
#define MBARRIER_WAIT_PARITY(mbar_smem_addr, phase_parity) do { \
    uint32_t _mbar = (uint32_t)(mbar_smem_addr); \
    uint32_t _parity = (uint32_t)(phase_parity); \
    uint32_t _done; \
    asm volatile( \
        "{\n\t.reg .pred p;\n\t" \
        "mbarrier.try_wait.parity.acquire.cta.shared::cta.b64 p, [%1], %2;\n\t" \
        "selp.b32 %0, 1, 0, p;\n\t}" \
        : "=r"(_done) : "r"(_mbar), "r"(_parity) : "memory"); \
    if (!_done) { \
        asm volatile( \
            "{\n\t.reg .pred P1;\n\t" \
            "WAIT_LOOP_%=:\n\t" \
            "mbarrier.try_wait.parity.acquire.cta.shared::cta.b64 P1, [%0], %1, 0x989680;\n\t" \
            "@P1 bra.uni WAIT_DONE_%=;\n\t" \
            "bra.uni WAIT_LOOP_%=;\n\t" \
            "WAIT_DONE_%=:\n\t}" \
            :: "r"(_mbar), "r"(_parity) : "memory"); \
    } \
} while(0)

// ---------------------------------------------------------------------------
// merged pre-pass: one launch.
// blocks [0,4096): cvt x rows; [4096,7168): transpose Wqkv; [7168,8192): Wproj
// ---------------------------------------------------------------------------
__device__ __forceinline__ void transpose_tile(const float* __restrict__ in,
                                               __half* __restrict__ out,
                                               int N, int n0, int k0,
                                               float (*t)[33], int tid)
{
    #pragma unroll
    for (int i = 0; i < 8; i++) {
        int idx = i * 128 + tid;
        int r = idx >> 5, c = idx & 31;
        t[r][c] = in[(size_t)(k0 + r) * N + n0 + c];
    }
    __syncthreads();
    int nl = tid >> 2, g = tid & 3;
    uint4 o;
    o.x = h2u(__floats2half2_rn(t[2*g][nl],      t[2*g+1][nl]));
    o.y = h2u(__floats2half2_rn(t[2*g+8][nl],    t[2*g+9][nl]));
    o.z = h2u(__floats2half2_rn(t[2*g+16][nl],   t[2*g+17][nl]));
    o.w = h2u(__floats2half2_rn(t[2*g+24][nl],   t[2*g+25][nl]));
    int n = n0 + nl;
    int nt = n >> 7, kt = k0 >> 6, r = n & 127;
    int ch = ((k0 >> 5) & 1) ^ (r & 1);
    *(uint4*)(out + ((size_t)(nt * 16 + kt) << 13) + (r << 6) + (ch << 5) + g * 8) = o;
}

__global__ __launch_bounds__(128) void prep_kernel(
    const float* __restrict__ x, const float* __restrict__ Wqkv,
    const float* __restrict__ Wproj,
    __half* __restrict__ xt, __half* __restrict__ wq, __half* __restrict__ wp)
{
    __shared__ float t[32][33];
    const int bi = blockIdx.x, tid = threadIdx.x;
    if (bi < 4096) {
        // cvt x: block = one row, thread = one 8-half unit
        int row = bi, uc = tid;
        int cb = (uc >> 2) << 5, g = uc & 3;
        const float* src = x + (size_t)row * CC + cb + 2 * g;
        float2 v0 = *(const float2*)(src);
        float2 v1 = *(const float2*)(src + 8);
        float2 v2 = *(const float2*)(src + 16);
        float2 v3 = *(const float2*)(src + 24);
        uint4 o;
        o.x = h2u(__floats2half2_rn(v0.x, v0.y));
        o.y = h2u(__floats2half2_rn(v1.x, v1.y));
        o.z = h2u(__floats2half2_rn(v2.x, v2.y));
        o.w = h2u(__floats2half2_rn(v3.x, v3.y));
        int mt = row >> 7, kt = cb >> 6, r = row & 127;
        int ch = ((cb >> 5) & 1) ^ (r & 1);
        *(uint4*)(xt + ((size_t)(mt * 16 + kt) << 13) + (r << 6) + (ch << 5) + g * 8) = o;
    } else if (bi < 4096 + 3072) {
        int b2 = bi - 4096;
        transpose_tile(Wqkv, wq, 3 * CC, (b2 >> 5) << 5, (b2 & 31) << 5, t, tid);
    } else {
        int b2 = bi - 7168;
        transpose_tile(Wproj, wp, CC, (b2 >> 5) << 5, (b2 & 31) << 5, t, tid);
    }
}

// ---------------------------------------------------------------------------
// fp16 GEMM compute (R12 config: 8 warps 2x4, warp tile 64x32).
// Tiles [128 rows][128 B], row-parity chunk swizzle. sxor = (gi&1)<<6.
// ---------------------------------------------------------------------------
#define TILE_B 16384

#define GEMM_COMPUTE16(Asb, Bsb)                                                 \
    _Pragma("unroll")                                                            \
    for (int kc = 0; kc < 2; kc++) {                                             \
        const int co = (kc * 64 + gc * 16) ^ sxor;                               \
        uint4 alo[4], ahi[4], bf[4];                                             \
        _Pragma("unroll")                                                        \
        for (int tm = 0; tm < 4; tm++) {                                         \
            int r = wm + tm * 16 + gi;                                           \
            alo[tm] = *(const uint4*)((Asb) + r * 128 + co);                     \
            ahi[tm] = *(const uint4*)((Asb) + (r + 8) * 128 + co);               \
        }                                                                        \
        _Pragma("unroll")                                                        \
        for (int tn = 0; tn < 4; tn++) {                                         \
            int n = wn + tn * 8 + gi;                                            \
            bf[tn] = *(const uint4*)((Bsb) + n * 128 + co);                      \
        }                                                                        \
        _Pragma("unroll")                                                        \
        for (int tm = 0; tm < 4; tm++)                                           \
            _Pragma("unroll")                                                    \
            for (int tn = 0; tn < 4; tn++) {                                     \
                mma16(C[tm][tn], alo[tm].x, ahi[tm].x, alo[tm].y, ahi[tm].y,     \
                      bf[tn].x, bf[tn].y);                                       \
                mma16(C[tm][tn], alo[tm].z, ahi[tm].z, alo[tm].w, ahi[tm].w,     \
                      bf[tn].z, bf[tn].w);                                       \
            }                                                                    \
    }

#define GEMM_SMEM (128 + 6*TILE_B)   // 98432 B

// ---------------------------------------------------------------------------
// Kernel 1: QKV GEMM (fp16, bulk-copy 3-stage, 256 thr, warp tile 64x32)
// ---------------------------------------------------------------------------
__global__ __launch_bounds__(256, 2) void qkv_mma_kernel(const float* __restrict__ bias)
{
    extern __shared__ char smc[];
    const uint32_t sb = smem_to_u32(smc);
    const char* tA = smc + 128;
    const char* tB = smc + 128 + 3 * TILE_B;

    const int tid  = threadIdx.x;
    const int lane = tid & 31;
    const int warp = tid >> 5;
    const int gi = lane >> 2, gc = lane & 3;
    const int sxor = (gi & 1) << 6;
    const int wm = (warp >> 2) * 64;
    const int wn = (warp & 3) * 32;
    const int m0 = blockIdx.y * 128, n0 = blockIdx.x * 128;

    if (tid == 0) {
        MBARRIER_INIT(sb + 0, 1);
        MBARRIER_INIT(sb + 8, 1);
        MBARRIER_INIT(sb + 16, 1);
    }
    __syncthreads();

#define Q_ISSUE(s, kt)                                                          \
    {                                                                           \
        MBARRIER_EXPECT_TX(sb + 8 * (s), 2 * TILE_B);                           \
        bulk_g2s(sb + 128 + (s) * TILE_B,                                       \
                 g_xt + ((size_t)(blockIdx.y * 16 + (kt)) << 13), TILE_B,       \
                 sb + 8 * (s));                                                 \
        bulk_g2s(sb + 128 + 3 * TILE_B + (s) * TILE_B,                          \
                 g_wqkvT + ((size_t)(blockIdx.x * 16 + (kt)) << 13), TILE_B,    \
                 sb + 8 * (s));                                                 \
    }

    if (tid == 0) { Q_ISSUE(0, 0); Q_ISSUE(1, 1); }

    float C[4][4][4] = {};
    int ph0 = 0, ph1 = 0, ph2 = 0;

    for (int it = 0; it < 16; it++) {
        const int s = it % 3;
        int ph = (s == 0) ? ph0 : (s == 1) ? ph1 : ph2;
        MBARRIER_WAIT_PARITY(sb + 8 * s, ph);
        if (s == 0) ph0 ^= 1; else if (s == 1) ph1 ^= 1; else ph2 ^= 1;
        __syncthreads();
        if (tid == 0 && it + 2 < 16) { int s2 = (it + 2) % 3; Q_ISSUE(s2, it + 2); }
        const char* Asb = tA + s * TILE_B;
        const char* Bsb = tB + s * TILE_B;
        GEMM_COMPUTE16(Asb, Bsb);
    }

    #pragma unroll
    for (int tm = 0; tm < 4; tm++) {
        #pragma unroll
        for (int tn = 0; tn < 4; tn++) {
            #pragma unroll
            for (int half_ = 0; half_ < 2; half_++) {
                int m = m0 + wm + tm * 16 + gi + half_ * 8;
                int n = n0 + wn + tn * 8 + 2 * gc;
                float v0 = C[tm][tn][half_ * 2 + 0] + bias[n];
                float v1 = C[tm][tn][half_ * 2 + 1] + bias[n + 1];
                int b = m >> 11, t = m & 2047;
                int h = n / 192;
                int r = n - h * 192;
                int d = r & 63;
                int bh = (b << 4) + h;
                if (r < 64) {
                    __half2 hv = __floats2half2_rn(v0 * 0.125f, v1 * 0.125f);
                    *(__half2*)(g_q + ((size_t)bh << 17) + ((size_t)t << 6) + hpos(d)) = hv;
                } else if (r < 128) {
                    __half2 hv = __floats2half2_rn(v0, v1);
                    int pos = hpos(d) ^ ((t & 1) << 5);
                    *(__half2*)(g_k + ((size_t)bh << 17) + ((size_t)t << 6) + pos) = hv;
                } else {
                    size_t tbase = ((size_t)(bh * 32 + (t >> 6)) << 12);
                    int tp = hpos(t & 63);
                    g_vt[tbase + ((size_t)d << 6) + tp]              = __float2half_rn(v0);
                    g_vt[tbase + ((size_t)(d + 1) << 6) + (tp ^ 32)] = __float2half_rn(v1);
                }
            }
        }
    }
}

// ---------------------------------------------------------------------------
// Kernel 2: causal flash attention. 128-key stages (two 64-key sub-tiles),
// bulk-copy 2-stage, P in registers. One sync per 128 keys.
// ---------------------------------------------------------------------------
#define KTILE2 16384
#define ATTN_SMEM (128 + 4*KTILE2)   // 65664 B

__global__ __launch_bounds__(256, 2) void attn_mma_kernel()
{
    extern __shared__ char smc[];
    const uint32_t sb = smem_to_u32(smc);
    const char* tK  = smc + 128;                 // [2][16384]
    const char* tVt = smc + 128 + 2 * KTILE2;    // [2][16384]

    const int bh = blockIdx.y;
    const int tid = threadIdx.x;
    const int lane = tid & 31;
    const int warp = tid >> 5;
    const int gi = lane >> 2, gc = lane & 3;
    const int sxor = (gi & 1) << 6;
    const int i0 = warp * 16 + gi;

    const __half* Kg  = g_k  + ((size_t)bh << 17);
    const __half* Vtg = g_vt + ((size_t)bh << 17);

    if (tid == 0) { MBARRIER_INIT(sb + 0, 1); MBARRIER_INIT(sb + 8, 1); }
    __syncthreads();

    int islot = 0, wslot = 0, phw0 = 0, phw1 = 0;

#define A_ISSUE(kt2_)                                                           \
    {                                                                           \
        int s_ = islot & 1;                                                     \
        if (tid == 0) {                                                         \
            MBARRIER_EXPECT_TX(sb + 8 * s_, 2 * KTILE2);                        \
            bulk_g2s(sb + 128 + s_ * KTILE2, Kg + ((size_t)(kt2_) << 13),       \
                     KTILE2, sb + 8 * s_);                                      \
            bulk_g2s(sb + 128 + 2 * KTILE2 + s_ * KTILE2,                       \
                     Vtg + ((size_t)(kt2_) << 13), KTILE2, sb + 8 * s_);        \
        }                                                                       \
        islot++;                                                                \
    }

    for (int pi = 0; pi < 2; pi++) {
        const int qt = pi ? (15 - (int)blockIdx.x) : (int)blockIdx.x;
        const __half* Qg = g_q + ((size_t)bh << 17) + ((size_t)qt << 13);

        __syncthreads();   // all warps done with previous pi's stage reads
        A_ISSUE(0);

        uint4 qa[2], qb[2];
        #pragma unroll
        for (int qc = 0; qc < 2; qc++) {
            qa[qc] = *(const uint4*)(Qg + i0 * 64 + qc * 32 + gc * 8);
            qb[qc] = *(const uint4*)(Qg + (i0 + 8) * 64 + qc * 32 + gc * 8);
        }

        float O[8][4] = {};
        float m0r = -1e30f, m1r = -1e30f, l0r = 0.f, l1r = 0.f;

        for (int kt2 = 0; kt2 <= qt; kt2++) {
            const int s = wslot & 1;
            int ph = s ? phw1 : phw0;
            MBARRIER_WAIT_PARITY(sb + 8 * s, ph);
            if (s) phw1 ^= 1; else phw0 ^= 1;
            wslot++;
            __syncthreads();   // all warps done reading stage s^1
            if (kt2 < qt) A_ISSUE(kt2 + 1);

            #pragma unroll
            for (int sub = 0; sub < 2; sub++) {
                const int kt = 2 * kt2 + sub;     // 64-key tile index
                const bool active = (kt * 64 <= qt * 128 + warp * 16 + 15);
                if (!active) continue;
                const char* sKb  = tK + s * KTILE2 + sub * 8192;
                const char* sVtb = tVt + s * KTILE2 + sub * 8192;

                // ---- S = Q @ K^T ----
                float S[8][4] = {};
                #pragma unroll
                for (int qc = 0; qc < 2; qc++) {
                    const int co = (qc * 64 + gc * 16) ^ sxor;
                    #pragma unroll
                    for (int nt = 0; nt < 8; nt++) {
                        int n = nt * 8 + gi;
                        uint4 kb = *(const uint4*)(sKb + n * 128 + co);
                        mma16(S[nt], qa[qc].x, qb[qc].x, qa[qc].y, qb[qc].y, kb.x, kb.y);
                        mma16(S[nt], qa[qc].z, qb[qc].z, qa[qc].w, qb[qc].w, kb.z, kb.w);
                    }
                }

                if (kt >= 2 * qt) {   // diagonal region: causal mask
                    int ig0 = qt * 128 + i0;
                    #pragma unroll
                    for (int nt = 0; nt < 8; nt++) {
                        int j0 = kt * 64 + nt * 8 + 2 * gc;
                        if (j0 > ig0)         S[nt][0] = -1e30f;
                        if (j0 + 1 > ig0)     S[nt][1] = -1e30f;
                        if (j0 > ig0 + 8)     S[nt][2] = -1e30f;
                        if (j0 + 1 > ig0 + 8) S[nt][3] = -1e30f;
                    }
                }

                // ---- online softmax, P -> registers ----
                float mx0 = -1e30f, mx1 = -1e30f;
                #pragma unroll
                for (int nt = 0; nt < 8; nt++) {
                    mx0 = fmaxf(mx0, fmaxf(S[nt][0], S[nt][1]));
                    mx1 = fmaxf(mx1, fmaxf(S[nt][2], S[nt][3]));
                }
                mx0 = fmaxf(mx0, __shfl_xor_sync(0xffffffffu, mx0, 1));
                mx0 = fmaxf(mx0, __shfl_xor_sync(0xffffffffu, mx0, 2));
                mx1 = fmaxf(mx1, __shfl_xor_sync(0xffffffffu, mx1, 1));
                mx1 = fmaxf(mx1, __shfl_xor_sync(0xffffffffu, mx1, 2));

                float mn0 = fmaxf(m0r, mx0), mn1 = fmaxf(m1r, mx1);
                float c0 = __expf(m0r - mn0), c1 = __expf(m1r - mn1);

                uint32_t phL[8], phH[8];
                float ls0 = 0.f, ls1 = 0.f;
                #pragma unroll
                for (int nt = 0; nt < 8; nt++) {
                    float p0 = __expf(S[nt][0] - mn0);
                    float p1 = __expf(S[nt][1] - mn0);
                    float p2 = __expf(S[nt][2] - mn1);
                    float p3 = __expf(S[nt][3] - mn1);
                    ls0 += p0 + p1;
                    ls1 += p2 + p3;
                    phL[nt] = h2u(__floats2half2_rn(p0, p1));
                    phH[nt] = h2u(__floats2half2_rn(p2, p3));
                }
                ls0 += __shfl_xor_sync(0xffffffffu, ls0, 1);
                ls0 += __shfl_xor_sync(0xffffffffu, ls0, 2);
                ls1 += __shfl_xor_sync(0xffffffffu, ls1, 1);
                ls1 += __shfl_xor_sync(0xffffffffu, ls1, 2);
                l0r = l0r * c0 + ls0;
                l1r = l1r * c1 + ls1;
                m0r = mn0; m1r = mn1;

                #pragma unroll
                for (int nt = 0; nt < 8; nt++) {
                    O[nt][0] *= c0; O[nt][1] *= c0;
                    O[nt][2] *= c1; O[nt][3] *= c1;
                }

                // ---- O += P @ V ----
                #pragma unroll
                for (int c = 0; c < 2; c++) {
                    const int co = (c * 64 + gc * 16) ^ sxor;
                    uint4 vb[8];
                    #pragma unroll
                    for (int ntd = 0; ntd < 8; ntd++)
                        vb[ntd] = *(const uint4*)(sVtb + (ntd * 8 + gi) * 128 + co);
                    #pragma unroll
                    for (int h = 0; h < 2; h++) {
                        int q0 = 4 * c + 2 * h;
                        uint32_t a0 = phL[q0], a1 = phH[q0];
                        uint32_t a2 = phL[q0 + 1], a3 = phH[q0 + 1];
                        #pragma unroll
                        for (int ntd = 0; ntd < 8; ntd++)
                            mma16(O[ntd], a0, a1, a2, a3,
                                  h ? vb[ntd].z : vb[ntd].x,
                                  h ? vb[ntd].w : vb[ntd].y);
                    }
                }
            }
        }

        float inv0 = 1.f / l0r, inv1 = 1.f / l1r;
        __half* Og = g_att + ((size_t)bh << 17) + ((size_t)qt << 13);
        #pragma unroll
        for (int nt = 0; nt < 8; nt++) {
            int d0 = nt * 8 + 2 * gc;
            int pos = hpos(d0) ^ ((i0 & 1) << 5);
            *(__half2*)(Og + i0 * 64 + pos) =
                __floats2half2_rn(O[nt][0] * inv0, O[nt][1] * inv0);
            *(__half2*)(Og + (i0 + 8) * 64 + pos) =
                __floats2half2_rn(O[nt][2] * inv1, O[nt][3] * inv1);
        }
    }
}

// ---------------------------------------------------------------------------
// Kernel 3: proj GEMM (fp16, bulk-copy 3-stage, 256 thr, warp tile 64x32)
// ---------------------------------------------------------------------------
__global__ __launch_bounds__(256, 2) void proj_mma_kernel(const float* __restrict__ bias,
                                                          float* __restrict__ out)
{
    extern __shared__ char smc[];
    const uint32_t sb = smem_to_u32(smc);
    const char* tA = smc + 128;
    const char* tB = smc + 128 + 3 * TILE_B;

    const int tid  = threadIdx.x;
    const int lane = tid & 31;
    const int warp = tid >> 5;
    const int gi = lane >> 2, gc = lane & 3;
    const int sxor = (gi & 1) << 6;
    const int wm = (warp >> 2) * 64;
    const int wn = (warp & 3) * 32;
    const int m0 = blockIdx.y * 128, n0 = blockIdx.x * 128;
    const int bb = m0 >> 11, t0 = m0 & 2047;

    if (tid == 0) {
        MBARRIER_INIT(sb + 0, 1);
        MBARRIER_INIT(sb + 8, 1);
        MBARRIER_INIT(sb + 16, 1);
    }
    __syncthreads();

#define P_ISSUE(s, it_)                                                          \
    {                                                                            \
        MBARRIER_EXPECT_TX(sb + 8 * (s), 2 * TILE_B);                            \
        bulk_g2s(sb + 128 + (s) * TILE_B,                                        \
                 g_att + ((size_t)((bb << 4) + (it_)) << 17) + (size_t)t0 * 64,  \
                 TILE_B, sb + 8 * (s));                                          \
        bulk_g2s(sb + 128 + 3 * TILE_B + (s) * TILE_B,                           \
                 g_wprojT + ((size_t)(blockIdx.x * 16 + (it_)) << 13), TILE_B,   \
                 sb + 8 * (s));                                                  \
    }

    if (tid == 0) { P_ISSUE(0, 0); P_ISSUE(1, 1); }

    float C[4][4][4] = {};
    int ph0 = 0, ph1 = 0, ph2 = 0;

    for (int it = 0; it < 16; it++) {
        const int s = it % 3;
        int ph = (s == 0) ? ph0 : (s == 1) ? ph1 : ph2;
        MBARRIER_WAIT_PARITY(sb + 8 * s, ph);
        if (s == 0) ph0 ^= 1; else if (s == 1) ph1 ^= 1; else ph2 ^= 1;
        __syncthreads();
        if (tid == 0 && it + 2 < 16) { int s2 = (it + 2) % 3; P_ISSUE(s2, it + 2); }
        const char* Asb = tA + s * TILE_B;
        const char* Bsb = tB + s * TILE_B;
        GEMM_COMPUTE16(Asb, Bsb);
    }

    #pragma unroll
    for (int tm = 0; tm < 4; tm++) {
        #pragma unroll
        for (int tn = 0; tn < 4; tn++) {
            #pragma unroll
            for (int e = 0; e < 4; e++) {
                int mm = m0 + wm + tm * 16 + gi + ((e >= 2) ? 8 : 0);
                int n = n0 + wn + tn * 8 + 2 * gc + (e & 1);
                out[(size_t)mm * CC + n] = C[tm][tn][e] + bias[n];
            }
        }
    }
}

// ---------------------------------------------------------------------------
extern "C" void kernel_launch(void* const* d_in, const int* in_sizes, int n_in,
                              void* d_out, int out_size)
{
    const float* x     = (const float*)d_in[0];
    const float* Wqkv  = (const float*)d_in[1];
    const float* bqkv  = (const float*)d_in[2];
    const float* Wproj = (const float*)d_in[3];
    const float* bproj = (const float*)d_in[4];
    float* out = (float*)d_out;

    cudaFuncSetAttribute(qkv_mma_kernel,
                         cudaFuncAttributeMaxDynamicSharedMemorySize, GEMM_SMEM);
    cudaFuncSetAttribute(proj_mma_kernel,
                         cudaFuncAttributeMaxDynamicSharedMemorySize, GEMM_SMEM);
    cudaFuncSetAttribute(attn_mma_kernel,
                         cudaFuncAttributeMaxDynamicSharedMemorySize, ATTN_SMEM);

    __half* xt; __half* wq; __half* wp;
    cudaGetSymbolAddress((void**)&xt, g_xt);
    cudaGetSymbolAddress((void**)&wq, g_wqkvT);
    cudaGetSymbolAddress((void**)&wp, g_wprojT);

    prep_kernel<<<8192, 128>>>(x, Wqkv, Wproj, xt, wq, wp);

    qkv_mma_kernel<<<dim3(24, 32), 256, GEMM_SMEM>>>(bqkv);
    attn_mma_kernel<<<dim3(8, 32), 256, ATTN_SMEM>>>();
    proj_mma_kernel<<<dim3(8, 32), 256, GEMM_SMEM>>>(bproj, out);
}